// round 11
// baseline (speedup 1.0000x reference)
#include <cuda_runtime.h>
#include <cstdint>

#define BB 20
#define LL 20
#define VV 100000
#define CSZ 8
#define MAXNB 3
#define PAD_LO 288
#define PAD_HI 192

// ---------------------------------------------------------------------------
// One 8-CTA cluster; batches are processed fully locally, only scalar losses
// cross CTAs.
//   CTA r owns nb = (r<4 ? 2 : 3) batches starting at gb = (r<4 ? 2r : 8+3(r-4)).
//   Each CTA: gather its own batches' P into LOCAL smem (800-1200 scattered
//   loads spread over 8 SMs), run the 29-step anti-diagonal wavefront DP
//   (warps 0-1; 16-lane segments = one batch each; lane c owns DP columns
//   2c+1, 2c+2; one segmented shfl/step), sum its per-batch losses to one
//   float, and deliver it to rank 0 via st.shared::cluster + remote
//   mbarrier.arrive (release). Rank 0 acquires via try_wait and writes out.
//   Cluster arrive at start / wait at end -> barrier latency hidden.
// ---------------------------------------------------------------------------
__global__ void __cluster_dims__(CSZ, 1, 1) __launch_bounds__(320)
calcs_local_kernel(
    const float* __restrict__ topic_prob,
    const int*   __restrict__ hard_label,
    float*       __restrict__ out)
{
    __shared__ float4 s_buf4[(PAD_LO + MAXNB * 400 + PAD_HI) / 4];
    __shared__ float  s_loss[MAXNB];
    __shared__ float  s_slots[CSZ];
    __shared__ unsigned long long s_mbar;
    float* s_P = ((float*)s_buf4) + PAD_LO;

    const int tid = threadIdx.x;
    unsigned int rank;
    asm("mov.u32 %0, %%cluster_ctarank;" : "=r"(rank));

    unsigned int mbar_la;
    asm("{ .reg .u64 t; cvta.to.shared.u64 t, %1; cvt.u32.u64 %0, t; }"
        : "=r"(mbar_la) : "l"((void*)&s_mbar));

    if (rank == 0) {
        if (tid == 0)
            asm volatile("mbarrier.init.shared.b64 [%0], %1;"
                         :: "r"(mbar_la), "r"(8u) : "memory");
        __syncthreads();    // init before this CTA's arrive
    }
    // all CTAs arrive now; waits happen at the end (hidden)
    asm volatile("barrier.cluster.arrive.aligned;" ::: "memory");

    const int nb = (rank < 4) ? 2 : 3;
    const int gb = (rank < 4) ? 2 * (int)rank : 8 + 3 * ((int)rank - 4);
    const int total = nb * 400;

    // ---- gather own batches into LOCAL smem ----
    #pragma unroll
    for (int it = 0; it < 4; ++it) {
        const int rel = tid + it * 320;
        if (rel < total) {
            const int k  = rel % LL;
            const int bj = rel / LL;                 // lb*20 + j
            const int b  = gb + bj / LL;
            const int lab = __ldg(&hard_label[b * LL + k]);
            const int idx = lab < 0 ? 0 : (lab > (VV - 1) ? (VV - 1) : lab);
            s_P[rel] = __ldg(&topic_prob[(size_t)(gb * LL + bj) * VV + idx]);
        }
    }
    __syncthreads();

    // ---- DP: warps 0-1, one batch per 16-lane segment ----
    const int warp = tid >> 5;
    const int lane = tid & 31;
    const int sub  = lane & 15;
    const int half = lane >> 4;

    if (warp < 2 && 2 * warp < nb) {
        const int  lbr     = 2 * warp + half;            // requested local batch
        const bool writeok = (lbr < nb);
        const int  lbc     = writeok ? lbr : (nb - 1);   // clamped (dup harmless)
        const int  B0 = gb + 2 * warp;
        const int  B1 = gb + ((2 * warp + 1 < nb) ? 2 * warp + 1 : nb - 1);

        const int l0 = (lane < LL) ? __ldg(&hard_label[B0 * LL + lane]) : -1;
        const unsigned bal0 = __ballot_sync(0xFFFFFFFFu, (lane < LL) && (l0 >= 0));
        const int l1 = (lane < LL) ? __ldg(&hard_label[B1 * LL + lane]) : -1;
        const unsigned bal1 = __ballot_sync(0xFFFFFFFFu, (lane < LL) && (l1 >= 0));

        const unsigned bal = half ? bal1 : bal0;
        const int len = __popc(bal & 0xFFFFFu);
        const int c   = sub;

        const int  base  = lbc * 400 - 18 * c - LL;      // local s_P index at t=0
        const bool capA  = (2 * c + 1 == len);
        const bool capB  = (2 * c + 2 == len);
        const bool valid = (c < 10);

        float prevA = 0.0f, prevB = 0.0f, dleft = 0.0f, result = 0.0f;

        if (bal0 == 0xFFFFFu && bal1 == 0xFFFFFu) {
            // fast path: all masks set (always for this data)
            #pragma unroll
            for (int t = 1; t <= LL + 9; ++t) {
                float left = __shfl_up_sync(0xFFFFFFFFu, prevB, 1, 16);
                if (sub == 0) left = 0.0f;
                const float diag = dleft;
                dleft = left;

                const int  j   = t - c;
                const bool act = valid && (j >= 1) && (j <= LL);

                const float2 p2 = *(const float2*)(s_P + base + t * LL);

                const float Ma = fmaxf(left, prevA);
                const float vA = fmaf(p2.x, diag + 1.0f - Ma, Ma);
                const float Mb = fmaxf(vA, prevB);
                const float vB = fmaf(p2.y, prevA + 1.0f - Mb, Mb);

                if (act) {
                    if (j == len) {
                        if (capA) result = vA;
                        if (capB) result = vB;
                    }
                    prevA = vA;
                    prevB = vB;
                }
            }
        } else {
            // general path: per-cell mask zeroing
            const unsigned bitA = (bal >> (2 * c)) & 1u;
            const unsigned bitB = (bal >> (2 * c + 1)) & 1u;
            #pragma unroll
            for (int t = 1; t <= LL + 9; ++t) {
                float left = __shfl_up_sync(0xFFFFFFFFu, prevB, 1, 16);
                if (sub == 0) left = 0.0f;
                const float diag = dleft;
                dleft = left;

                const int  j   = t - c;
                const bool act = valid && (j >= 1) && (j <= LL);
                const int  js  = (j < 1) ? 1 : (j > LL ? LL : j);
                const unsigned mj = (bal >> (js - 1)) & 1u;

                const float2 p2 = *(const float2*)(s_P + base + t * LL);

                const float Ma = fmaxf(left, prevA);
                float vA = fmaf(p2.x, diag + 1.0f - Ma, Ma);
                vA = (mj & bitA) ? vA : 0.0f;
                const float Mb = fmaxf(vA, prevB);
                float vB = fmaf(p2.y, prevA + 1.0f - Mb, Mb);
                vB = (mj & bitB) ? vB : 0.0f;

                if (act) {
                    if (j == len) {
                        if (capA) result = vA;
                        if (capB) result = vB;
                    }
                    prevA = vA;
                    prevB = vB;
                }
            }
        }

        if (len > 0) {
            if ((capA || capB) && valid && writeok)
                s_loss[lbc] = -logf(result / (float)len);
        } else if (sub == 0 && writeok) {
            s_loss[lbc] = -logf(0.0f / 0.0f);   // 0/0 -> nan, matches reference
        }
    }
    __syncthreads();

    if (rank != 0) {
        // wait pairs the start arrive; instant by now, guarantees rank0's
        // mbarrier init is visible before our remote store/arrive
        asm volatile("barrier.cluster.wait.aligned;" ::: "memory");
        if (tid == 0) {
            float p = s_loss[0] + s_loss[1];
            if (nb == 3) p += s_loss[2];
            unsigned int slot_la, slot_ra, mbar_ra;
            asm("{ .reg .u64 t; cvta.to.shared.u64 t, %1; cvt.u32.u64 %0, t; }"
                : "=r"(slot_la) : "l"((void*)&s_slots[rank]));
            asm("mapa.shared::cluster.u32 %0, %1, 0;" : "=r"(slot_ra) : "r"(slot_la));
            asm("mapa.shared::cluster.u32 %0, %1, 0;" : "=r"(mbar_ra) : "r"(mbar_la));
            asm volatile("st.shared::cluster.f32 [%0], %1;"
                         :: "r"(slot_ra), "f"(p) : "memory");
            asm volatile("mbarrier.arrive.shared::cluster.b64 _, [%0];"
                         :: "r"(mbar_ra) : "memory");   // release: orders the store
        }
        return;
    }

    // ---- rank 0: combine ----
    asm volatile("barrier.cluster.wait.aligned;" ::: "memory");
    if (tid == 0) {
        float p = s_loss[0] + s_loss[1];   // nb == 2 for rank 0
        s_slots[0] = p;
        asm volatile("mbarrier.arrive.shared.b64 _, [%0];"
                     :: "r"(mbar_la) : "memory");       // local arrival (8th)
        // acquire-wait for all 8 arrivals (phase parity 0)
        asm volatile(
            "{\n\t"
            ".reg .pred p;\n\t"
            "WL%=:\n\t"
            "mbarrier.try_wait.parity.acquire.cluster.shared::cta.b64 p, [%0], %1, 0x989680;\n\t"
            "@p bra WD%=;\n\t"
            "bra WL%=;\n\t"
            "WD%=:\n\t"
            "}"
            :: "r"(mbar_la), "r"(0u) : "memory");

        float s = 0.0f;
        #pragma unroll
        for (int r = 0; r < CSZ; ++r) s += s_slots[r];
        out[0] = s * (1.0f / (float)BB);
    }
}

extern "C" void kernel_launch(void* const* d_in, const int* in_sizes, int n_in,
                              void* d_out, int out_size) {
    const float* topic_prob = (const float*)d_in[0];
    const int*   hard_label = (const int*)d_in[1];
    float*       out        = (float*)d_out;
    calcs_local_kernel<<<CSZ, 320>>>(topic_prob, hard_label, out);
}